// round 7
// baseline (speedup 1.0000x reference)
#include <cuda_runtime.h>

#define SNE_H 1080
#define SNE_W 1920
#define SNE_HW (SNE_H * SNE_W)
#define BX 32
#define BYT 8                  // thread rows
#define ROWS (BYT * 2)         // pixel rows per block = 16
#define TX (BX + 2)            // 34
#define TY (ROWS + 2)          // 18
#define NTHR (BX * BYT)        // 256

__device__ __forceinline__ bool f_isnan(float x) {
    return (__float_as_uint(x) & 0x7fffffffu) > 0x7f800000u;
}
// true iff x finite and > 0 (x never negative where used)
__device__ __forceinline__ bool f_pos_finite(float x) {
    return (__float_as_uint(x) - 1u) < 0x7f7fffffu;
}
__device__ __forceinline__ float frcp_fast(float x) {   // 0 -> +inf, like 1/Z
    float r; asm("rcp.approx.f32 %0, %1;" : "=f"(r) : "f"(x)); return r;
}

__device__ __forceinline__ float4 make_px(int vv, int uu, float z0,
                                          float cx, float cy, float inv_fx) {
    float y = z0 * ((float)vv - cy) * inv_fx;
    const bool neg = (y <= 0.f);
    const float z = neg ? 0.f : z0;
    y = neg ? 0.f : y;
    const float x = z0 * ((float)uu - cx) * inv_fx;   // X not masked (matches ref)
    return make_float4(x, y, z, frcp_fast(z));
}

struct N3 { float x, y, z; };

// One pixel's normal; neighborhood read directly from the shared tile
// (center at tile[r][cc]).  Compiler CSEs the overlapping loads between
// the two calls per thread.
__device__ __forceinline__ N3 compute_px(const float4 (*__restrict__ tile)[TX],
                                         int r, int cc, float fx, float fy) {
    const float4 c = tile[r][cc];
    const float dl = tile[r][cc - 1].w, dr = tile[r][cc + 1].w;
    const float du = tile[r - 1][cc].w, dd = tile[r + 1][cc].w;

    const float nxt = fx * (dr - dl);
    const float nyt = fy * (dd - du);

    // cos(atan(t)+pi) = -1/sqrt(1+t^2), sin = -t/sqrt(1+t^2).
    // fminf clamp safe: t NaN => all gates fail => snz=0 => s NaN => bad path.
    const float t = __fdividef(nyt, nxt);
    const float at = fminf(fabsf(t), 1e18f);
    const float rp = rsqrtf(fmaf(at, at, 1.f));
    const float a = -rp;
    const float b = -copysignf(at * rp, t);

    const float nn = fmaf(nxt, nxt, nyt * nyt);
    float S = 0.f, snz = 0.f;
#pragma unroll
    for (int k = 0; k < 9; ++k) {
        if (k == 4) continue;
        const int dv = k / 3 - 1, du2 = k % 3 - 1;   // compile-time after unroll
        const float4 nb = tile[r + dv][cc + du2];
        const float Xd = c.x - nb.x;
        const float Yd = c.y - nb.y;
        const float Zd = c.z - nb.z;
        const float nzi = __fdividef(fmaf(nxt, Xd, nyt * Yd), Zd);
        const float arg = fmaf(nzi, nzi, nn);
        // Gate equivalent to the reference's per-component NaN masking:
        // arg pos-finite <=> rsqrt(arg) pos-finite <=> all contribs finite.
        if (f_pos_finite(arg)) {
            const float rn = rsqrtf(arg);
            S   += rn;
            snz  = fmaf(nzi, rn, snz);
        }
    }
    const float snx = nxt * S;
    const float sny = nyt * S;

    // theta = -atan(s): sin = -s/sqrt(1+s^2), cos = 1/sqrt(1+s^2).
    // Ternary clamp preserves NaN (s NaN must reach the bad path).
    const float s = __fdividef(fmaf(snx, a, sny * b), snz);
    float as_ = fabsf(s);
    as_ = (as_ > 1e18f) ? 1e18f : as_;
    const float rs = rsqrtf(fmaf(as_, as_, 1.f));
    const float st = -copysignf(as_ * rs, s);
    float nz = rs;
    float nx = st * a;
    float ny = st * b;

    const bool bad = f_isnan(nz);
    nx = bad ? 0.f : nx;
    ny = bad ? 0.f : ny;
    nz = bad ? -1.f : nz;
    const float sgn = (ny > 0.f) ? -1.f : 1.f;
    return { nx * sgn, ny * sgn, nz * sgn };
}

__global__ void __launch_bounds__(NTHR)
sne_kernel(const float* __restrict__ depth,
           const float* __restrict__ cam,
           float* __restrict__ out)
{
    __shared__ float4 tile[TY][TX];   // (X, Y, Z_masked, D=1/Z)

    const int tx = threadIdx.x, ty = threadIdx.y;
    const int tid = ty * BX + tx;
    const int bu = blockIdx.x * BX, bv = blockIdx.y * ROWS;

    const float fx = cam[0], cx = cam[2], fy = cam[4], cy = cam[5];
    const float inv_fx = frcp_fast(fx);

    // ---- Fill 34x18 tile (612 elems, 256 threads -> 3 rounds) ----
#pragma unroll
    for (int base = 0; base < TX * TY; base += NTHR) {
        const int i = base + tid;
        if (i < TX * TY) {
            const int lv = i / TX, lu = i - lv * TX;
            const int vv = bv + lv - 1, uu = bu + lu - 1;
            float4 t = make_float4(0.f, 0.f, 0.f, 0.f);
            if ((unsigned)vv < SNE_H && (unsigned)uu < SNE_W)
                t = make_px(vv, uu, __ldg(depth + vv * SNE_W + uu), cx, cy, inv_fx);
            tile[lv][lu] = t;
        }
    }
    __syncthreads();

    const int u = bu + tx;
    const int v0 = bv + 2 * ty;     // pixel A row; B = v0 + 1

    const N3 pA = compute_px(tile, 2 * ty + 1, tx + 1, fx, fy);
    const N3 pB = compute_px(tile, 2 * ty + 2, tx + 1, fx, fy);

    if (v0 < SNE_H) {               // tail guard: 1080 % 16 == 8
        const int idx = v0 * SNE_W + u;
        out[idx]              = pA.x;
        out[SNE_HW + idx]     = pA.y;
        out[2 * SNE_HW + idx] = pA.z;
    }
    if (v0 + 1 < SNE_H) {
        const int idx = (v0 + 1) * SNE_W + u;
        out[idx]              = pB.x;
        out[SNE_HW + idx]     = pB.y;
        out[2 * SNE_HW + idx] = pB.z;
    }
}

extern "C" void kernel_launch(void* const* d_in, const int* in_sizes, int n_in,
                              void* d_out, int out_size) {
    const float* depth = (const float*)d_in[0];
    const float* cam   = (const float*)d_in[1];
    float* out = (float*)d_out;
    dim3 blk(BX, BYT);
    dim3 grd(SNE_W / BX, (SNE_H + ROWS - 1) / ROWS);
    sne_kernel<<<grd, blk>>>(depth, cam, out);
}

// round 9
// speedup vs baseline: 1.0275x; 1.0275x over previous
#include <cuda_runtime.h>

#define SNE_H 1080
#define SNE_W 1920
#define SNE_HW (SNE_H * SNE_W)
#define BX 32
#define BYT 8                  // thread rows
#define ROWS (BYT * 2)         // pixel rows per block = 16
#define TX (BX + 2)            // 34
#define TY (ROWS + 2)          // 18
#define NTHR (BX * BYT)        // 256

__device__ __forceinline__ bool f_isnan(float x) {
    return (__float_as_uint(x) & 0x7fffffffu) > 0x7f800000u;
}
// true iff x finite and > 0 (x never negative where used)
__device__ __forceinline__ bool f_pos_finite(float x) {
    return (__float_as_uint(x) - 1u) < 0x7f7fffffu;
}
__device__ __forceinline__ float frcp_fast(float x) {   // 0 -> +inf, like 1/Z
    float r; asm("rcp.approx.f32 %0, %1;" : "=f"(r) : "f"(x)); return r;
}

__device__ __forceinline__ float4 make_px(int vv, int uu, float z0,
                                          float cx, float cy, float inv_fx) {
    float y = z0 * ((float)vv - cy) * inv_fx;
    const bool neg = (y <= 0.f);
    const float z = neg ? 0.f : z0;
    y = neg ? 0.f : y;
    const float x = z0 * ((float)uu - cx) * inv_fx;   // X not masked (matches ref)
    return make_float4(x, y, z, frcp_fast(z));
}

struct N3 { float x, y, z; };

// One pixel's normal; neighborhood read directly from the shared tile.
__device__ __forceinline__ N3 compute_px(const float4 (*__restrict__ tile)[TX],
                                         int r, int cc, float fx, float fy) {
    const float4 c = tile[r][cc];
    const float dl = tile[r][cc - 1].w, dr = tile[r][cc + 1].w;
    const float du = tile[r - 1][cc].w, dd = tile[r + 1][cc].w;

    const float nxt = fx * (dr - dl);
    const float nyt = fy * (dd - du);

    // cos(atan(t)+pi) = -1/sqrt(1+t^2), sin = -t/sqrt(1+t^2).
    // fminf clamp safe: t NaN => all gates fail => snz=0 => s NaN => bad path.
    const float t = __fdividef(nyt, nxt);
    const float at = fminf(fabsf(t), 1e18f);
    const float rp = rsqrtf(fmaf(at, at, 1.f));
    const float a = -rp;
    const float b = -copysignf(at * rp, t);

    const float nn = fmaf(nxt, nxt, nyt * nyt);
    float S = 0.f, snz = 0.f;
#pragma unroll
    for (int k = 0; k < 9; ++k) {
        if (k == 4) continue;
        const int dv = k / 3 - 1, du2 = k % 3 - 1;   // compile-time after unroll
        const float4 nb = tile[r + dv][cc + du2];
        const float Xd = c.x - nb.x;
        const float Yd = c.y - nb.y;
        const float Zd = c.z - nb.z;
        const float nzi = __fdividef(fmaf(nxt, Xd, nyt * Yd), Zd);
        const float arg = fmaf(nzi, nzi, nn);
        const float rn  = rsqrtf(arg);   // UNCONDITIONAL -> predication, not branches
        // Gate equivalent to the reference's per-component NaN masking:
        // arg pos-finite <=> all contributions finite; else all contribs are 0.
        if (f_pos_finite(arg)) {
            S   += rn;
            snz  = fmaf(nzi, rn, snz);
        }
    }
    const float snx = nxt * S;
    const float sny = nyt * S;

    // theta = -atan(s): sin = -s/sqrt(1+s^2), cos = 1/sqrt(1+s^2).
    // Ternary clamp preserves NaN (s NaN must reach the bad path).
    const float s = __fdividef(fmaf(snx, a, sny * b), snz);
    float as_ = fabsf(s);
    as_ = (as_ > 1e18f) ? 1e18f : as_;
    const float rs = rsqrtf(fmaf(as_, as_, 1.f));
    const float st = -copysignf(as_ * rs, s);
    float nz = rs;
    float nx = st * a;
    float ny = st * b;

    const bool bad = f_isnan(nz);
    nx = bad ? 0.f : nx;
    ny = bad ? 0.f : ny;
    nz = bad ? -1.f : nz;
    const float sgn = (ny > 0.f) ? -1.f : 1.f;
    return { nx * sgn, ny * sgn, nz * sgn };
}

__global__ void __launch_bounds__(NTHR, 6)
sne_kernel(const float* __restrict__ depth,
           const float* __restrict__ cam,
           float* __restrict__ out)
{
    __shared__ float4 tile[TY][TX];   // (X, Y, Z_masked, D=1/Z)

    const int tx = threadIdx.x, ty = threadIdx.y;
    const int tid = ty * BX + tx;
    const int bu = blockIdx.x * BX, bv = blockIdx.y * ROWS;

    const float fx = cam[0], cx = cam[2], fy = cam[4], cy = cam[5];
    const float inv_fx = frcp_fast(fx);

    // ---- Fill 34x18 tile (612 elems, 256 threads -> 3 rounds) ----
#pragma unroll
    for (int base = 0; base < TX * TY; base += NTHR) {
        const int i = base + tid;
        if (i < TX * TY) {
            const int lv = i / TX, lu = i - lv * TX;
            const int vv = bv + lv - 1, uu = bu + lu - 1;
            float4 t = make_float4(0.f, 0.f, 0.f, 0.f);
            if ((unsigned)vv < SNE_H && (unsigned)uu < SNE_W)
                t = make_px(vv, uu, __ldg(depth + vv * SNE_W + uu), cx, cy, inv_fx);
            tile[lv][lu] = t;
        }
    }
    __syncthreads();

    const int u = bu + tx;
    const int v0 = bv + 2 * ty;     // pixel A row; B = v0 + 1

    const N3 pA = compute_px(tile, 2 * ty + 1, tx + 1, fx, fy);
    const N3 pB = compute_px(tile, 2 * ty + 2, tx + 1, fx, fy);

    if (v0 < SNE_H) {               // tail guard: 1080 % 16 == 8
        const int idx = v0 * SNE_W + u;
        out[idx]              = pA.x;
        out[SNE_HW + idx]     = pA.y;
        out[2 * SNE_HW + idx] = pA.z;
    }
    if (v0 + 1 < SNE_H) {
        const int idx = (v0 + 1) * SNE_W + u;
        out[idx]              = pB.x;
        out[SNE_HW + idx]     = pB.y;
        out[2 * SNE_HW + idx] = pB.z;
    }
}

extern "C" void kernel_launch(void* const* d_in, const int* in_sizes, int n_in,
                              void* d_out, int out_size) {
    const float* depth = (const float*)d_in[0];
    const float* cam   = (const float*)d_in[1];
    float* out = (float*)d_out;
    dim3 blk(BX, BYT);
    dim3 grd(SNE_W / BX, (SNE_H + ROWS - 1) / ROWS);
    sne_kernel<<<grd, blk>>>(depth, cam, out);
}

// round 10
// speedup vs baseline: 1.5675x; 1.5255x over previous
#include <cuda_runtime.h>

#define SNE_H 1080
#define SNE_W 1920
#define SNE_HW (SNE_H * SNE_W)
#define BX 32
#define BYT 8                  // thread rows
#define ROWS (BYT * 2)         // pixel rows per block = 16
#define TX (BX + 2)            // 34
#define TY (ROWS + 2)          // 18
#define NTHR (BX * BYT)        // 256

__device__ __forceinline__ bool f_isnan(float x) {
    return (__float_as_uint(x) & 0x7fffffffu) > 0x7f800000u;
}
// true iff x finite and > 0 (x never negative where used)
__device__ __forceinline__ bool f_pos_finite(float x) {
    return (__float_as_uint(x) - 1u) < 0x7f7fffffu;
}
__device__ __forceinline__ float frcp_fast(float x) {   // 0 -> +inf, like 1/Z
    float r; asm("rcp.approx.f32 %0, %1;" : "=f"(r) : "f"(x)); return r;
}

__device__ __forceinline__ float4 make_px(int vv, int uu, float z0,
                                          float cx, float cy, float inv_fx) {
    float y = z0 * ((float)vv - cy) * inv_fx;
    const bool neg = (y <= 0.f);
    const float z = neg ? 0.f : z0;
    y = neg ? 0.f : y;
    const float x = z0 * ((float)uu - cx) * inv_fx;   // X not masked (matches ref)
    return make_float4(x, y, z, frcp_fast(z));
}

struct N3 { float x, y, z; };

// One pixel's normal from the shared tile; center at tile[r][cc].
// This is the R4 code path (measured fastest compute variant).
__device__ __forceinline__ N3 compute_px(const float4 (*__restrict__ tile)[TX],
                                         int r, int cc, float fx, float fy) {
    const float4 c = tile[r][cc];
    const float dl = tile[r][cc - 1].w, dr = tile[r][cc + 1].w;
    const float du = tile[r - 1][cc].w, dd = tile[r + 1][cc].w;

    const float nxt = fx * (dr - dl);
    const float nyt = fy * (dd - du);

    // cos(atan(t)+pi) = -1/sqrt(1+t^2), sin = -t/sqrt(1+t^2); ternary keeps NaN.
    const float t = __fdividef(nyt, nxt);
    float at = fabsf(t);
    at = (at > 1e18f) ? 1e18f : at;
    const float rp = rsqrtf(fmaf(at, at, 1.f));
    const float a = -rp;
    const float b = -copysignf(at * rp, t);

    const float nn = fmaf(nxt, nxt, nyt * nyt);
    float snx = 0.f, sny = 0.f, snz = 0.f;
#pragma unroll
    for (int k = 0; k < 9; ++k) {
        if (k == 4) continue;
        const int dv = k / 3 - 1, du2 = k % 3 - 1;   // compile-time after unroll
        const float4 nb = tile[r + dv][cc + du2];
        const float Xd = c.x - nb.x;
        const float Yd = c.y - nb.y;
        const float Zd = c.z - nb.z;
        const float nzi = __fdividef(fmaf(nxt, Xd, nyt * Yd), Zd);
        const float rn  = rsqrtf(fmaf(nzi, nzi, nn));
        // Equivalent to the reference's per-component NaN-masked accumulation:
        //  rn normal => all finite, accumulate; rn in {0, inf, NaN} => contribs 0.
        if (f_pos_finite(rn)) {
            snx = fmaf(nxt, rn, snx);
            sny = fmaf(nyt, rn, sny);
            snz = fmaf(nzi, rn, snz);
        }
    }

    // theta = -atan(s): sin = -s/sqrt(1+s^2), cos = 1/sqrt(1+s^2).
    const float s = __fdividef(fmaf(snx, a, sny * b), snz);
    float as_ = fabsf(s);
    as_ = (as_ > 1e18f) ? 1e18f : as_;
    const float rs = rsqrtf(fmaf(as_, as_, 1.f));
    const float st = -copysignf(as_ * rs, s);
    float nz = rs;
    float nx = st * a;
    float ny = st * b;

    const bool bad = f_isnan(nz);
    nx = bad ? 0.f : nx;
    ny = bad ? 0.f : ny;
    nz = bad ? -1.f : nz;
    const float sgn = (ny > 0.f) ? -1.f : 1.f;
    return { nx * sgn, ny * sgn, nz * sgn };
}

__global__ void __launch_bounds__(NTHR)
sne_kernel(const float* __restrict__ depth,
           const float* __restrict__ cam,
           float* __restrict__ out)
{
    __shared__ float4 tile[TY][TX];   // (X, Y, Z_masked, D=1/Z)

    const int tx = threadIdx.x, ty = threadIdx.y;
    const int tid = ty * BX + tx;
    const int bu = blockIdx.x * BX, bv = blockIdx.y * ROWS;

    const int u = bu + tx;
    const int v0 = bv + 2 * ty;     // pixel A row; B = v0 + 1
    const float cy = __ldg(cam + 5);

    // ---- Fast path: whole block in the fully-masked half ----
    // A pixel row v is masked iff Z0*(v-cy)/fx <= 0 <=> v <= cy (depth > 0).
    // If every neighbor row of every pixel in this block (max row bv+ROWS) is
    // masked, the entire 3x3 Z/D neighborhood is {0, +inf}; both the reference
    // and the general path below then provably emit exactly (0, 0, -1):
    // interior: nxt = fx*(inf-inf) = NaN poisons all 8 gates; borders: +/-inf
    // gradients make every norm infinite, so all contributions mask to 0 and
    // theta = NaN -> bad path. Block-uniform branch, taken before any barrier.
    if ((float)(bv + ROWS) <= cy) {
        if (v0 < SNE_H) {
            const int idx = v0 * SNE_W + u;
            out[idx]              = 0.f;
            out[SNE_HW + idx]     = 0.f;
            out[2 * SNE_HW + idx] = -1.f;
        }
        if (v0 + 1 < SNE_H) {
            const int idx = (v0 + 1) * SNE_W + u;
            out[idx]              = 0.f;
            out[SNE_HW + idx]     = 0.f;
            out[2 * SNE_HW + idx] = -1.f;
        }
        return;
    }

    const float fx = cam[0], cx = cam[2], fy = cam[4];
    const float inv_fx = frcp_fast(fx);

    // ---- Fill 34x18 tile (612 elems, 256 threads -> 3 rounds) ----
#pragma unroll
    for (int base = 0; base < TX * TY; base += NTHR) {
        const int i = base + tid;
        if (i < TX * TY) {
            const int lv = i / TX, lu = i - lv * TX;
            const int vv = bv + lv - 1, uu = bu + lu - 1;
            float4 t = make_float4(0.f, 0.f, 0.f, 0.f);
            if ((unsigned)vv < SNE_H && (unsigned)uu < SNE_W)
                t = make_px(vv, uu, __ldg(depth + vv * SNE_W + uu), cx, cy, inv_fx);
            tile[lv][lu] = t;
        }
    }
    __syncthreads();

    const N3 pA = compute_px(tile, 2 * ty + 1, tx + 1, fx, fy);
    const N3 pB = compute_px(tile, 2 * ty + 2, tx + 1, fx, fy);

    if (v0 < SNE_H) {               // tail guard: 1080 % 16 == 8
        const int idx = v0 * SNE_W + u;
        out[idx]              = pA.x;
        out[SNE_HW + idx]     = pA.y;
        out[2 * SNE_HW + idx] = pA.z;
    }
    if (v0 + 1 < SNE_H) {
        const int idx = (v0 + 1) * SNE_W + u;
        out[idx]              = pB.x;
        out[SNE_HW + idx]     = pB.y;
        out[2 * SNE_HW + idx] = pB.z;
    }
}

extern "C" void kernel_launch(void* const* d_in, const int* in_sizes, int n_in,
                              void* d_out, int out_size) {
    const float* depth = (const float*)d_in[0];
    const float* cam   = (const float*)d_in[1];
    float* out = (float*)d_out;
    dim3 blk(BX, BYT);
    dim3 grd(SNE_W / BX, (SNE_H + ROWS - 1) / ROWS);
    sne_kernel<<<grd, blk>>>(depth, cam, out);
}